// round 12
// baseline (speedup 1.0000x reference)
#include <cuda_runtime.h>
#include <cuda_bf16.h>
#include <cuda_fp16.h>
#include <math.h>
#include <stdint.h>

#define BATCH 4096
#define HDIM  256
#define KEXP  16
#define DDIM  512
#define IDIM  8
#define EDIM  64
#define LN_EPS 1e-5f

// ---------------------------------------------------------------------------
// Scratch (__device__ globals; no cudaMalloc)
// ---------------------------------------------------------------------------
__device__ __half g_w2h[(size_t)KEXP * DDIM * DDIM];   // 8MB  [k][e][d] fp16
__device__ __half g_h2[(size_t)BATCH * KEXP * DDIM];   // 64MB [b][k][d]
__device__ __half g_gw1t[HDIM * HDIM];                 // 128KB [j][i] fp16
__device__ __half g_hph[(size_t)BATCH * HDIM];         // 2MB  h_prev fp16
__device__ float g_C[(size_t)BATCH * HDIM];            // 4MB tanh(h_prev@gw1+gb1)

// ---------------------------------------------------------------------------
// Helpers
// ---------------------------------------------------------------------------
__device__ __forceinline__ uint32_t smem_u32(const void* p) {
    uint32_t a;
    asm("{ .reg .u64 t; cvta.to.shared.u64 t, %1; cvt.u32.u64 %0, t; }"
        : "=r"(a) : "l"(p));
    return a;
}
__device__ __forceinline__ void cpasync16(uint32_t dst, const void* src) {
    asm volatile("cp.async.cg.shared.global [%0], [%1], 16;" :: "r"(dst), "l"(src));
}
#define CP_COMMIT() asm volatile("cp.async.commit_group;" ::: "memory")
#define CP_WAIT1()  asm volatile("cp.async.wait_group 1;" ::: "memory")

__device__ __forceinline__ void ldsm4(uint32_t* r, uint32_t addr) {
    asm volatile("ldmatrix.sync.aligned.m8n8.x4.shared.b16 {%0,%1,%2,%3}, [%4];"
        : "=r"(r[0]), "=r"(r[1]), "=r"(r[2]), "=r"(r[3]) : "r"(addr));
}
// fp16 x fp16 -> fp32 accum
__device__ __forceinline__ void mma16816h(float* d, const uint32_t* a,
                                          const uint32_t* b) {
    asm volatile(
        "mma.sync.aligned.m16n8k16.row.col.f32.f16.f16.f32 "
        "{%0,%1,%2,%3}, {%4,%5,%6,%7}, {%8,%9}, {%0,%1,%2,%3};"
        : "+f"(d[0]), "+f"(d[1]), "+f"(d[2]), "+f"(d[3])
        : "r"(a[0]), "r"(a[1]), "r"(a[2]), "r"(a[3]), "r"(b[0]), "r"(b[1]));
}
// fast tanh: 2 MUFU + fast div, rel err ~1e-6
__device__ __forceinline__ float ftanh(float x) {
    float ax = fabsf(x);
    float e  = __expf(-2.f * ax);
    float r  = __fdividef(1.f - e, 1.f + e);
    return copysignf(r, x);
}

// ---------------------------------------------------------------------------
// Prep kernel:
//   blocks [0,512)   : w2 transpose -> fp16 g_w2h (128d x 64e tile each)
//   blocks [512,520) : gw1 transpose -> fp16 g_gw1t (128i x 64j tile each)
//   blocks [520,552) : h_prev -> fp16 g_hph
// ---------------------------------------------------------------------------
__global__ __launch_bounds__(256) void k_prep(
    const float* __restrict__ w2, const float* __restrict__ gw1,
    const float* __restrict__ h_prev)
{
    __shared__ float s[64][129];
    const int bi = blockIdx.x;
    const int tid = threadIdx.x;

    if (bi < 512) {
        const int k = bi >> 5;
        const int t = bi & 31;
        const int e0 = (t & 7) * 64;
        const int dblk = (t >> 3) * 128;

        for (int i = tid; i < 128 * 64; i += 256) {
            int dl = i >> 6, el = i & 63;
            s[el][dl] = w2[((size_t)k * DDIM + dblk + dl) * DDIM + e0 + el];
        }
        __syncthreads();

        const int el = tid >> 2, cp = tid & 3;
        uint32_t hv[16];
#pragma unroll
        for (int jj = 0; jj < 16; jj++) {
            __half a = __float2half_rn(s[el][cp * 32 + 2 * jj]);
            __half b = __float2half_rn(s[el][cp * 32 + 2 * jj + 1]);
            hv[jj] = ((uint32_t)__half_as_ushort(b) << 16) | __half_as_ushort(a);
        }
        const size_t base = ((size_t)k * DDIM + e0 + el) * DDIM + dblk + cp * 32;
        uint4* dh = (uint4*)&g_w2h[base];
        dh[0] = make_uint4(hv[0], hv[1], hv[2], hv[3]);
        dh[1] = make_uint4(hv[4], hv[5], hv[6], hv[7]);
        dh[2] = make_uint4(hv[8], hv[9], hv[10], hv[11]);
        dh[3] = make_uint4(hv[12], hv[13], hv[14], hv[15]);
    } else if (bi < 520) {
        const int t = bi - 512;            // 0..7
        const int j0 = (t & 3) * 64;
        const int i0 = (t >> 2) * 128;

        for (int i = tid; i < 128 * 64; i += 256) {
            int il = i >> 6, jl = i & 63;
            s[jl][il] = gw1[(size_t)(i0 + il) * HDIM + j0 + jl];
        }
        __syncthreads();

        const int jl = tid >> 2, cp = tid & 3;
        uint32_t hv[16];
#pragma unroll
        for (int jj = 0; jj < 16; jj++) {
            __half a = __float2half_rn(s[jl][cp * 32 + 2 * jj]);
            __half b = __float2half_rn(s[jl][cp * 32 + 2 * jj + 1]);
            hv[jj] = ((uint32_t)__half_as_ushort(b) << 16) | __half_as_ushort(a);
        }
        const size_t base = (size_t)(j0 + jl) * HDIM + i0 + cp * 32;
        uint4* dh = (uint4*)&g_gw1t[base];
        dh[0] = make_uint4(hv[0], hv[1], hv[2], hv[3]);
        dh[1] = make_uint4(hv[4], hv[5], hv[6], hv[7]);
        dh[2] = make_uint4(hv[8], hv[9], hv[10], hv[11]);
        dh[3] = make_uint4(hv[12], hv[13], hv[14], hv[15]);
    } else {
        const int t = bi - 520;            // 0..31
        const size_t base = (size_t)t * 32768;
#pragma unroll 4
        for (int i = tid; i < 8192; i += 256) {
            float4 v = *(const float4*)&h_prev[base + i * 4];
            __half2 h0 = __floats2half2_rn(v.x, v.y);
            __half2 h1 = __floats2half2_rn(v.z, v.w);
            uint2 o = make_uint2(*reinterpret_cast<uint32_t*>(&h0),
                                 *reinterpret_cast<uint32_t*>(&h1));
            *(uint2*)&g_hph[base + i * 4] = o;
        }
    }
}

// ---------------------------------------------------------------------------
// gate1 HMMA GEMM: g_C = tanh(h_prev @ gw1 + gb1).  M=4096, N=256, K=256.
// 32 CTAs, tile 128x256, 512 threads, k-chunk 32, 3-stage ring.
// ---------------------------------------------------------------------------
#define GSTAGE 30720
#define GATE_SMEM (3 * GSTAGE)

__global__ __launch_bounds__(512, 1) void k_gate(const float* __restrict__ gb1)
{
    extern __shared__ char dsm[];
    const int m0 = blockIdx.x * 128;
    const int tid = threadIdx.x, lane = tid & 31, wid = tid >> 5;
    const int wm = wid >> 3, wn = wid & 7;
    const uint32_t sbase = smem_u32(dsm);

    const char* srcp[3];
    uint32_t dsto[3];
#pragma unroll
    for (int t = 0; t < 3; t++) {
        const int idx = tid + t * 512;
        if (idx < 512) {
            const int row = idx >> 2, seg = idx & 3;
            srcp[t] = (const char*)(g_hph + (size_t)(m0 + row) * HDIM) + seg * 16;
            dsto[t] = sbase + row * 80 + seg * 16;
        } else {
            const int j = idx - 512;
            const int row = j >> 2, seg = j & 3;
            srcp[t] = (const char*)(g_gw1t + (size_t)row * HDIM) + seg * 16;
            dsto[t] = sbase + 10240 + row * 80 + seg * 16;
        }
    }

    float acc[4][4][4];
#pragma unroll
    for (int i = 0; i < 4; i++)
#pragma unroll
        for (int j = 0; j < 4; j++)
#pragma unroll
            for (int q = 0; q < 4; q++) acc[i][j][q] = 0.f;

    const int arow = lane & 15, aseg = lane >> 4;
    const int brow = (lane & 7) + ((lane >> 4) & 1) * 8, bseg = (lane >> 3) & 1;
    const uint32_t offA = sbase + (wm * 64 + arow) * 80 + aseg * 16;
    const uint32_t offB = sbase + 10240 + (wn * 32 + brow) * 80 + bseg * 16;

#pragma unroll
    for (int t = 0; t < 3; t++) cpasync16(dsto[t], srcp[t]);
    CP_COMMIT();
#pragma unroll
    for (int t = 0; t < 3; t++) cpasync16(dsto[t] + GSTAGE, srcp[t] + 64);
    CP_COMMIT();

    for (int c = 0; c < 8; ++c) {
        CP_WAIT1();
        __syncthreads();

        if (c + 2 < 8) {
            const uint32_t so2 = (uint32_t)((c + 2) % 3) * GSTAGE;
            const int boff = (c + 2) * 64;
#pragma unroll
            for (int t = 0; t < 3; t++)
                cpasync16(dsto[t] + so2, srcp[t] + boff);
        }
        CP_COMMIT();

        const uint32_t so = (uint32_t)(c % 3) * GSTAGE;
#pragma unroll
        for (int ks = 0; ks < 2; ks++) {
            uint32_t bh[8];
            ldsm4(bh,     offB + so + ks * 32);
            ldsm4(bh + 4, offB + so + ks * 32 + 16 * 80);
#pragma unroll
            for (int mi = 0; mi < 4; mi++) {
                uint32_t ah[4];
                ldsm4(ah, offA + so + ks * 32 + mi * 16 * 80);
#pragma unroll
                for (int ni = 0; ni < 4; ni++)
                    mma16816h(acc[mi][ni], ah, bh + ni * 2);
            }
        }
    }

    const int gid = lane >> 2, qid = lane & 3;
    const float* gbk = gb1 + wn * 32;
#pragma unroll
    for (int ni = 0; ni < 4; ni++) {
        const int ncol = ni * 8 + 2 * qid;
        const float bv0 = __ldg(&gbk[ncol]), bv1 = __ldg(&gbk[ncol + 1]);
#pragma unroll
        for (int mi = 0; mi < 4; mi++) {
            const int m = m0 + wm * 64 + mi * 16 + gid;
            float* dst = &g_C[(size_t)m * HDIM + wn * 32 + ncol];
            *(float2*)dst = make_float2(ftanh(acc[mi][ni][0] + bv0),
                                        ftanh(acc[mi][ni][1] + bv1));
            *(float2*)(dst + 8 * HDIM) = make_float2(ftanh(acc[mi][ni][2] + bv0),
                                                     ftanh(acc[mi][ni][3] + bv1));
        }
    }
}

// ---------------------------------------------------------------------------
// Main GEMM: 128x128 tile, 256 threads (8 warps, warp tile 64x32), k-chunk 32,
// 3-stage ring, __launch_bounds__(256,2) -> 2 CTAs/SM for latency overlap.
// Stage (20480B): A[128][80] @0, B[128][80] @10240.
// A generated in-kernel: tanh(x_ext*w1+b1) -> fp16. B via cp.async (fp16 w2h).
// ---------------------------------------------------------------------------
#define STAGE_BYTES 20480
#define CONST_OFF   (3 * STAGE_BYTES)               // 61440
#define GSMEM       (CONST_OFF + 512 + 2048 + 2048)  // 66048

__global__ __launch_bounds__(256, 2) void k_gemm_mma(
    const float* __restrict__ b2, const float* __restrict__ x_ext,
    const float* __restrict__ w1, const float* __restrict__ b1)
{
    extern __shared__ char dsm[];
    const int n0 = blockIdx.x * 128;
    const int m0 = blockIdx.y * 128;
    const int kx = blockIdx.z;
    const int tid = threadIdx.x, lane = tid & 31, wid = tid >> 5;
    const int wm = wid >> 2, wn = wid & 3;
    const uint32_t sbase = smem_u32(dsm);

    float* s_x  = (float*)(dsm + CONST_OFF);           // 128
    float* s_w1 = (float*)(dsm + CONST_OFF + 512);     // 512
    float* s_b1 = (float*)(dsm + CONST_OFF + 2560);    // 512

    if (tid < 128) s_x[tid] = x_ext[(size_t)(m0 + tid) * KEXP + kx];
    s_w1[tid] = w1[kx * DDIM + tid];
    s_w1[tid + 256] = w1[kx * DDIM + tid + 256];
    s_b1[tid] = b1[kx * DDIM + tid];
    s_b1[tid + 256] = b1[kx * DDIM + tid + 256];

    // cp.async B slots: 512 segs of 16B per stage, 2 per thread
    const char* srcp[2];
    uint32_t dsto[2];
#pragma unroll
    for (int t = 0; t < 2; t++) {
        const int idx = tid + t * 256;
        const int row = idx >> 2;        // 0..127
        const int seg = idx & 3;
        srcp[t] = (const char*)(g_w2h + ((size_t)(kx * DDIM + n0 + row)) * DDIM) + seg * 16;
        dsto[t] = sbase + 10240 + row * 80 + seg * 16;
    }

    // A-gen: thread -> row = tid>>1 (0..127), half = tid&1 (16 d values, 32B)
    const int gr = tid >> 1;
    const int gh = tid & 1;
    const uint32_t ga_rel = (uint32_t)(gr * 80 + gh * 32);

    float acc[4][4][4];
#pragma unroll
    for (int i = 0; i < 4; i++)
#pragma unroll
        for (int j = 0; j < 4; j++)
#pragma unroll
            for (int q = 0; q < 4; q++) acc[i][j][q] = 0.f;

    const int arow = lane & 15, aseg = lane >> 4;
    const int brow = (lane & 7) + ((lane >> 4) & 1) * 8, bseg = (lane >> 3) & 1;
    const uint32_t offA = sbase + (wm * 64 + arow) * 80 + aseg * 16;
    const uint32_t offB = sbase + 10240 + (wn * 32 + brow) * 80 + bseg * 16;

    __syncthreads();   // consts visible

    auto genA = [&](int c, uint32_t so) {
        const float x = s_x[gr];
        uint32_t hv[8];
#pragma unroll
        for (int i = 0; i < 8; i++) {
            const int j = c * 32 + gh * 16 + 2 * i;
            float v0 = ftanh(fmaf(x, s_w1[j],     s_b1[j]));
            float v1 = ftanh(fmaf(x, s_w1[j + 1], s_b1[j + 1]));
            __half2 h = __floats2half2_rn(v0, v1);
            hv[i] = *reinterpret_cast<uint32_t*>(&h);
        }
        *(uint4*)(dsm + ga_rel + so)      = make_uint4(hv[0], hv[1], hv[2], hv[3]);
        *(uint4*)(dsm + ga_rel + so + 16) = make_uint4(hv[4], hv[5], hv[6], hv[7]);
    };

    // prologue: chunks 0,1
    genA(0, 0);
    genA(1, STAGE_BYTES);
#pragma unroll
    for (int t = 0; t < 2; t++) cpasync16(dsto[t], srcp[t]);
    CP_COMMIT();
#pragma unroll
    for (int t = 0; t < 2; t++) cpasync16(dsto[t] + STAGE_BYTES, srcp[t] + 64);
    CP_COMMIT();

    for (int c = 0; c < 16; ++c) {
        CP_WAIT1();            // B chunk c landed
        __syncthreads();       // A chunk c visible; stage (c+2)%3 free

        if (c + 2 < 16) {
            const uint32_t so2 = (uint32_t)((c + 2) % 3) * STAGE_BYTES;
            genA(c + 2, so2);
            const int boff = (c + 2) * 64;
#pragma unroll
            for (int t = 0; t < 2; t++)
                cpasync16(dsto[t] + so2, srcp[t] + boff);
        }
        CP_COMMIT();

        const uint32_t so = (uint32_t)(c % 3) * STAGE_BYTES;
#pragma unroll
        for (int ks = 0; ks < 2; ks++) {
            uint32_t bh[8];
            ldsm4(bh,     offB + so + ks * 32);
            ldsm4(bh + 4, offB + so + ks * 32 + 16 * 80);
#pragma unroll
            for (int mi = 0; mi < 4; mi++) {
                uint32_t ah[4];
                ldsm4(ah, offA + so + ks * 32 + mi * 16 * 80);
#pragma unroll
                for (int ni = 0; ni < 4; ni++)
                    mma16816h(acc[mi][ni], ah, bh + ni * 2);
            }
        }
    }

    // epilogue: + b2, tanh, store fp16 to g_h2[b][k][d]
    const int gid = lane >> 2, qid = lane & 3;
    const float* b2k = b2 + kx * DDIM + n0 + wn * 32;
#pragma unroll
    for (int ni = 0; ni < 4; ni++) {
        const int ncol = ni * 8 + 2 * qid;
        const float bv0 = __ldg(&b2k[ncol]), bv1 = __ldg(&b2k[ncol + 1]);
#pragma unroll
        for (int mi = 0; mi < 4; mi++) {
            const int m = m0 + wm * 64 + mi * 16 + gid;
            const size_t base = (size_t)m * (KEXP * DDIM) + kx * DDIM + n0 + wn * 32 + ncol;
            __half2 v0 = __floats2half2_rn(ftanh(acc[mi][ni][0] + bv0),
                                           ftanh(acc[mi][ni][1] + bv1));
            __half2 v1 = __floats2half2_rn(ftanh(acc[mi][ni][2] + bv0),
                                           ftanh(acc[mi][ni][3] + bv1));
            *(__half2*)&g_h2[base] = v0;
            *(__half2*)&g_h2[base + (size_t)8 * (KEXP * DDIM)] = v1;
        }
    }
}

// ---------------------------------------------------------------------------
// Epilogue: fused gate logits+softmax, warp-per-expert LN, gate-weighted sum,
// theta0, x_prime.
// ---------------------------------------------------------------------------
__global__ __launch_bounds__(128) void k_epilogue(
    const float* __restrict__ ln_g, const float* __restrict__ ln_b,
    const float* __restrict__ theta0, const float* __restrict__ x_l,
    const float* __restrict__ gw2, const float* __restrict__ gb2,
    float* __restrict__ out)
{
    const int b = blockIdx.x;
    const int tid = threadIdx.x, lane = tid & 31, w = tid >> 5;
    __shared__ float s_gw2[HDIM * KEXP];
    __shared__ float s_C[HDIM];
    __shared__ float s_lg[8][16];
    __shared__ float s_g[16];
    __shared__ float s_part[4][512];
    __shared__ float s_theta[512];

#pragma unroll
    for (int i = 0; i < 8; i++)
        *(float4*)&s_gw2[(tid + i * 128) * 4] = *(const float4*)&gw2[(tid + i * 128) * 4];
    if (tid < 64)
        *(float4*)&s_C[tid * 4] = *(const float4*)&g_C[(size_t)b * HDIM + tid * 4];

    uint2 raw[4][4];
#pragma unroll
    for (int kk = 0; kk < 4; kk++) {
        const int k = w + kk * 4;
        const __half* src = g_h2 + (size_t)b * (KEXP * DDIM) + k * DDIM;
#pragma unroll
        for (int q = 0; q < 4; q++)
            raw[kk][q] = *(const uint2*)&src[q * 128 + lane * 4];
    }

    float4 lg[4], lb[4];
#pragma unroll
    for (int q = 0; q < 4; q++) {
        const int d = q * 128 + lane * 4;
        lg[q] = *(const float4*)&ln_g[d];
        lb[q] = *(const float4*)&ln_b[d];
    }
    __syncthreads();

    {
        const int k = tid & 15, jg = tid >> 4;
        float p = 0.f;
#pragma unroll
        for (int j = 0; j < 32; j++)
            p += s_C[jg * 32 + j] * s_gw2[(jg * 32 + j) * KEXP + k];
        s_lg[jg][k] = p;
    }
    __syncthreads();
    if (tid < 32) {
        const int k = lane & 15;
        float l = gb2[k];
#pragma unroll
        for (int jg = 0; jg < 8; jg++) l += s_lg[jg][k];
        float m = l;
#pragma unroll
        for (int o = 8; o > 0; o >>= 1) m = fmaxf(m, __shfl_xor_sync(0xffffffffu, m, o, 16));
        float e = expf(l - m);
        float s = e;
#pragma unroll
        for (int o = 8; o > 0; o >>= 1) s += __shfl_xor_sync(0xffffffffu, s, o, 16);
        if (lane < 16) s_g[k] = e / s;
    }

    float th[4][4];
#pragma unroll
    for (int q = 0; q < 4; q++)
#pragma unroll
        for (int j = 0; j < 4; j++) th[q][j] = 0.f;
    __syncthreads();

#pragma unroll
    for (int kk = 0; kk < 4; kk++) {
        const int k = w + kk * 4;
        float4 v[4];
        float s = 0.f, qq = 0.f;
#pragma unroll
        for (int q = 0; q < 4; q++) {
            float2 f0 = __half22float2(*reinterpret_cast<__half2*>(&raw[kk][q].x));
            float2 f1 = __half22float2(*reinterpret_cast<__half2*>(&raw[kk][q].y));
            v[q] = make_float4(f0.x, f0.y, f1.x, f1.y);
            s  += v[q].x + v[q].y + v[q].z + v[q].w;
            qq += v[q].x * v[q].x + v[q].y * v[q].y + v[q].z * v[q].z + v[q].w * v[q].w;
        }
#pragma unroll
        for (int o = 16; o > 0; o >>= 1) {
            s  += __shfl_xor_sync(0xffffffffu, s, o);
            qq += __shfl_xor_sync(0xffffffffu, qq, o);
        }
        const float mu = s * (1.f / 512.f);
        const float var = qq * (1.f / 512.f) - mu * mu;
        const float rs = rsqrtf(var + LN_EPS);
        const float gk = s_g[k];
#pragma unroll
        for (int q = 0; q < 4; q++) {
            th[q][0] += gk * ((v[q].x - mu) * rs * lg[q].x + lb[q].x);
            th[q][1] += gk * ((v[q].y - mu) * rs * lg[q].y + lb[q].y);
            th[q][2] += gk * ((v[q].z - mu) * rs * lg[q].z + lb[q].z);
            th[q][3] += gk * ((v[q].w - mu) * rs * lg[q].w + lb[q].w);
        }
    }

#pragma unroll
    for (int q = 0; q < 4; q++)
        *(float4*)&s_part[w][q * 128 + lane * 4] = make_float4(th[q][0], th[q][1], th[q][2], th[q][3]);
    __syncthreads();

    const int d0 = tid * 4;
    float4 p0 = *(float4*)&s_part[0][d0];
    float4 p1 = *(float4*)&s_part[1][d0];
    float4 p2 = *(float4*)&s_part[2][d0];
    float4 p3 = *(float4*)&s_part[3][d0];
    float4 t0 = *(const float4*)&theta0[d0];
    float4 t;
    t.x = p0.x + p1.x + p2.x + p3.x + t0.x;
    t.y = p0.y + p1.y + p2.y + p3.y + t0.y;
    t.z = p0.z + p1.z + p2.z + p3.z + t0.z;
    t.w = p0.w + p1.w + p2.w + p3.w + t0.w;
    *(float4*)&out[(size_t)BATCH * EDIM + (size_t)b * DDIM + d0] = t;
    *(float4*)&s_theta[d0] = t;
    __syncthreads();

    if (tid < EDIM) {
        float xp = 0.f;
#pragma unroll
        for (int i = 0; i < IDIM; i++)
            xp += x_l[b * IDIM + i] * s_theta[i * EDIM + tid];
        out[(size_t)b * EDIM + tid] = xp;
    }
}

// ---------------------------------------------------------------------------
extern "C" void kernel_launch(void* const* d_in, const int* in_sizes, int n_in,
                              void* d_out, int out_size)
{
    const float* h_prev = (const float*)d_in[0];
    const float* x_l    = (const float*)d_in[1];
    const float* x_ext  = (const float*)d_in[2];
    const float* w1     = (const float*)d_in[3];
    const float* b1     = (const float*)d_in[4];
    const float* w2     = (const float*)d_in[5];
    const float* b2     = (const float*)d_in[6];
    const float* gw1    = (const float*)d_in[7];
    const float* gb1    = (const float*)d_in[8];
    const float* gw2    = (const float*)d_in[9];
    const float* gb2    = (const float*)d_in[10];
    const float* ln_g   = (const float*)d_in[11];
    const float* ln_b   = (const float*)d_in[12];
    const float* theta0 = (const float*)d_in[13];
    float* out = (float*)d_out;

    cudaFuncSetAttribute(k_gemm_mma, cudaFuncAttributeMaxDynamicSharedMemorySize, GSMEM);
    cudaFuncSetAttribute(k_gate, cudaFuncAttributeMaxDynamicSharedMemorySize, GATE_SMEM);

    k_prep<<<552, 256>>>(w2, gw1, h_prev);
    k_gate<<<32, 512, GATE_SMEM>>>(gb1);
    k_gemm_mma<<<dim3(4, 32, KEXP), 256, GSMEM>>>(b2, x_ext, w1, b1);
    k_epilogue<<<BATCH, 128>>>(ln_g, ln_b, theta0, x_l, gw2, gb2, out);
}

// round 13
// speedup vs baseline: 1.0329x; 1.0329x over previous
#include <cuda_runtime.h>
#include <cuda_bf16.h>
#include <cuda_fp16.h>
#include <math.h>
#include <stdint.h>

#define BATCH 4096
#define HDIM  256
#define KEXP  16
#define DDIM  512
#define IDIM  8
#define EDIM  64
#define LN_EPS 1e-5f

// ---------------------------------------------------------------------------
// Scratch (__device__ globals; no cudaMalloc)
// ---------------------------------------------------------------------------
__device__ __half g_w2h[(size_t)KEXP * DDIM * DDIM];   // 8MB  [k][e][d] fp16
__device__ __half g_h2[(size_t)BATCH * KEXP * DDIM];   // 64MB [b][k][d]
__device__ __half g_gw1t[HDIM * HDIM];                 // 128KB [j][i] fp16
__device__ __half g_hph[(size_t)BATCH * HDIM];         // 2MB  h_prev fp16
__device__ float g_C[(size_t)BATCH * HDIM];            // 4MB tanh(h_prev@gw1+gb1)

// ---------------------------------------------------------------------------
// Helpers
// ---------------------------------------------------------------------------
__device__ __forceinline__ uint32_t smem_u32(const void* p) {
    uint32_t a;
    asm("{ .reg .u64 t; cvta.to.shared.u64 t, %1; cvt.u32.u64 %0, t; }"
        : "=r"(a) : "l"(p));
    return a;
}
__device__ __forceinline__ void cpasync16(uint32_t dst, const void* src) {
    asm volatile("cp.async.cg.shared.global [%0], [%1], 16;" :: "r"(dst), "l"(src));
}
#define CP_COMMIT() asm volatile("cp.async.commit_group;" ::: "memory")
#define CP_WAIT1()  asm volatile("cp.async.wait_group 1;" ::: "memory")

__device__ __forceinline__ void ldsm4(uint32_t* r, uint32_t addr) {
    asm volatile("ldmatrix.sync.aligned.m8n8.x4.shared.b16 {%0,%1,%2,%3}, [%4];"
        : "=r"(r[0]), "=r"(r[1]), "=r"(r[2]), "=r"(r[3]) : "r"(addr));
}
// fp16 x fp16 -> fp32 accum
__device__ __forceinline__ void mma16816h(float* d, const uint32_t* a,
                                          const uint32_t* b) {
    asm volatile(
        "mma.sync.aligned.m16n8k16.row.col.f32.f16.f16.f32 "
        "{%0,%1,%2,%3}, {%4,%5,%6,%7}, {%8,%9}, {%0,%1,%2,%3};"
        : "+f"(d[0]), "+f"(d[1]), "+f"(d[2]), "+f"(d[3])
        : "r"(a[0]), "r"(a[1]), "r"(a[2]), "r"(a[3]), "r"(b[0]), "r"(b[1]));
}
// fast tanh: 2 MUFU + fast div, rel err ~1e-6
__device__ __forceinline__ float ftanh(float x) {
    float ax = fabsf(x);
    float e  = __expf(-2.f * ax);
    float r  = __fdividef(1.f - e, 1.f + e);
    return copysignf(r, x);
}

// ---------------------------------------------------------------------------
// w2 transpose -> fp16 g_w2h: one 128d x 64e tile per block (512 blocks)
// ---------------------------------------------------------------------------
__global__ __launch_bounds__(256) void k_w2t(const float* __restrict__ w2)
{
    __shared__ float s[64][129];
    const int bi = blockIdx.x;
    const int tid = threadIdx.x;

    const int k = bi >> 5;
    const int t = bi & 31;
    const int e0 = (t & 7) * 64;
    const int dblk = (t >> 3) * 128;

    for (int i = tid; i < 128 * 64; i += 256) {
        int dl = i >> 6, el = i & 63;
        s[el][dl] = w2[((size_t)k * DDIM + dblk + dl) * DDIM + e0 + el];
    }
    __syncthreads();

    const int el = tid >> 2, cp = tid & 3;
    uint32_t hv[16];
#pragma unroll
    for (int jj = 0; jj < 16; jj++) {
        __half a = __float2half_rn(s[el][cp * 32 + 2 * jj]);
        __half b = __float2half_rn(s[el][cp * 32 + 2 * jj + 1]);
        hv[jj] = ((uint32_t)__half_as_ushort(b) << 16) | __half_as_ushort(a);
    }
    const size_t base = ((size_t)k * DDIM + e0 + el) * DDIM + dblk + cp * 32;
    uint4* dh = (uint4*)&g_w2h[base];
    dh[0] = make_uint4(hv[0], hv[1], hv[2], hv[3]);
    dh[1] = make_uint4(hv[4], hv[5], hv[6], hv[7]);
    dh[2] = make_uint4(hv[8], hv[9], hv[10], hv[11]);
    dh[3] = make_uint4(hv[12], hv[13], hv[14], hv[15]);
}

// ---------------------------------------------------------------------------
// Gate inputs: blocks [0,8) gw1 transpose -> fp16; blocks [8,40) h_prev -> fp16
// ---------------------------------------------------------------------------
__global__ __launch_bounds__(256) void k_gatein(
    const float* __restrict__ gw1, const float* __restrict__ h_prev)
{
    __shared__ float s[64][129];
    const int bi = blockIdx.x;
    const int tid = threadIdx.x;

    if (bi < 8) {
        const int j0 = (bi & 3) * 64;
        const int i0 = (bi >> 2) * 128;

        for (int i = tid; i < 128 * 64; i += 256) {
            int il = i >> 6, jl = i & 63;
            s[jl][il] = gw1[(size_t)(i0 + il) * HDIM + j0 + jl];
        }
        __syncthreads();

        const int jl = tid >> 2, cp = tid & 3;
        uint32_t hv[16];
#pragma unroll
        for (int jj = 0; jj < 16; jj++) {
            __half a = __float2half_rn(s[jl][cp * 32 + 2 * jj]);
            __half b = __float2half_rn(s[jl][cp * 32 + 2 * jj + 1]);
            hv[jj] = ((uint32_t)__half_as_ushort(b) << 16) | __half_as_ushort(a);
        }
        const size_t base = (size_t)(j0 + jl) * HDIM + i0 + cp * 32;
        uint4* dh = (uint4*)&g_gw1t[base];
        dh[0] = make_uint4(hv[0], hv[1], hv[2], hv[3]);
        dh[1] = make_uint4(hv[4], hv[5], hv[6], hv[7]);
        dh[2] = make_uint4(hv[8], hv[9], hv[10], hv[11]);
        dh[3] = make_uint4(hv[12], hv[13], hv[14], hv[15]);
    } else {
        const int t = bi - 8;              // 0..31
        const size_t base = (size_t)t * 32768;
#pragma unroll 4
        for (int i = tid; i < 8192; i += 256) {
            float4 v = *(const float4*)&h_prev[base + i * 4];
            __half2 h0 = __floats2half2_rn(v.x, v.y);
            __half2 h1 = __floats2half2_rn(v.z, v.w);
            uint2 o = make_uint2(*reinterpret_cast<uint32_t*>(&h0),
                                 *reinterpret_cast<uint32_t*>(&h1));
            *(uint2*)&g_hph[base + i * 4] = o;
        }
    }
}

// ---------------------------------------------------------------------------
// gate1 HMMA GEMM: g_C = tanh(h_prev @ gw1 + gb1).  M=4096, N=256, K=256.
// 32 CTAs, tile 128x256, 512 threads, k-chunk 32, 3-stage ring.
// ---------------------------------------------------------------------------
#define GSTAGE 30720
#define GATE_SMEM (3 * GSTAGE)

__global__ __launch_bounds__(512, 1) void k_gate(const float* __restrict__ gb1)
{
    extern __shared__ char dsm[];
    const int m0 = blockIdx.x * 128;
    const int tid = threadIdx.x, lane = tid & 31, wid = tid >> 5;
    const int wm = wid >> 3, wn = wid & 7;
    const uint32_t sbase = smem_u32(dsm);

    const char* srcp[3];
    uint32_t dsto[3];
#pragma unroll
    for (int t = 0; t < 3; t++) {
        const int idx = tid + t * 512;
        if (idx < 512) {
            const int row = idx >> 2, seg = idx & 3;
            srcp[t] = (const char*)(g_hph + (size_t)(m0 + row) * HDIM) + seg * 16;
            dsto[t] = sbase + row * 80 + seg * 16;
        } else {
            const int j = idx - 512;
            const int row = j >> 2, seg = j & 3;
            srcp[t] = (const char*)(g_gw1t + (size_t)row * HDIM) + seg * 16;
            dsto[t] = sbase + 10240 + row * 80 + seg * 16;
        }
    }

    float acc[4][4][4];
#pragma unroll
    for (int i = 0; i < 4; i++)
#pragma unroll
        for (int j = 0; j < 4; j++)
#pragma unroll
            for (int q = 0; q < 4; q++) acc[i][j][q] = 0.f;

    const int arow = lane & 15, aseg = lane >> 4;
    const int brow = (lane & 7) + ((lane >> 4) & 1) * 8, bseg = (lane >> 3) & 1;
    const uint32_t offA = sbase + (wm * 64 + arow) * 80 + aseg * 16;
    const uint32_t offB = sbase + 10240 + (wn * 32 + brow) * 80 + bseg * 16;

#pragma unroll
    for (int t = 0; t < 3; t++) cpasync16(dsto[t], srcp[t]);
    CP_COMMIT();
#pragma unroll
    for (int t = 0; t < 3; t++) cpasync16(dsto[t] + GSTAGE, srcp[t] + 64);
    CP_COMMIT();

    for (int c = 0; c < 8; ++c) {
        CP_WAIT1();
        __syncthreads();

        if (c + 2 < 8) {
            const uint32_t so2 = (uint32_t)((c + 2) % 3) * GSTAGE;
            const int boff = (c + 2) * 64;
#pragma unroll
            for (int t = 0; t < 3; t++)
                cpasync16(dsto[t] + so2, srcp[t] + boff);
        }
        CP_COMMIT();

        const uint32_t so = (uint32_t)(c % 3) * GSTAGE;
#pragma unroll
        for (int ks = 0; ks < 2; ks++) {
            uint32_t bh[8];
            ldsm4(bh,     offB + so + ks * 32);
            ldsm4(bh + 4, offB + so + ks * 32 + 16 * 80);
#pragma unroll
            for (int mi = 0; mi < 4; mi++) {
                uint32_t ah[4];
                ldsm4(ah, offA + so + ks * 32 + mi * 16 * 80);
#pragma unroll
                for (int ni = 0; ni < 4; ni++)
                    mma16816h(acc[mi][ni], ah, bh + ni * 2);
            }
        }
    }

    const int gid = lane >> 2, qid = lane & 3;
    const float* gbk = gb1 + wn * 32;
#pragma unroll
    for (int ni = 0; ni < 4; ni++) {
        const int ncol = ni * 8 + 2 * qid;
        const float bv0 = __ldg(&gbk[ncol]), bv1 = __ldg(&gbk[ncol + 1]);
#pragma unroll
        for (int mi = 0; mi < 4; mi++) {
            const int m = m0 + wm * 64 + mi * 16 + gid;
            float* dst = &g_C[(size_t)m * HDIM + wn * 32 + ncol];
            *(float2*)dst = make_float2(ftanh(acc[mi][ni][0] + bv0),
                                        ftanh(acc[mi][ni][1] + bv1));
            *(float2*)(dst + 8 * HDIM) = make_float2(ftanh(acc[mi][ni][2] + bv0),
                                                     ftanh(acc[mi][ni][3] + bv1));
        }
    }
}

// ---------------------------------------------------------------------------
// Main GEMM: 128x128 tile, 256 threads (8 warps, warp tile 64x32), k-chunk 32,
// 3-stage ring, 2 CTAs/SM.
// ---------------------------------------------------------------------------
#define STAGE_BYTES 20480
#define CONST_OFF   (3 * STAGE_BYTES)               // 61440
#define GSMEM       (CONST_OFF + 512 + 2048 + 2048)  // 66048

__global__ __launch_bounds__(256, 2) void k_gemm_mma(
    const float* __restrict__ b2, const float* __restrict__ x_ext,
    const float* __restrict__ w1, const float* __restrict__ b1)
{
    extern __shared__ char dsm[];
    const int n0 = blockIdx.x * 128;
    const int m0 = blockIdx.y * 128;
    const int kx = blockIdx.z;
    const int tid = threadIdx.x, lane = tid & 31, wid = tid >> 5;
    const int wm = wid >> 2, wn = wid & 3;
    const uint32_t sbase = smem_u32(dsm);

    float* s_x  = (float*)(dsm + CONST_OFF);
    float* s_w1 = (float*)(dsm + CONST_OFF + 512);
    float* s_b1 = (float*)(dsm + CONST_OFF + 2560);

    if (tid < 128) s_x[tid] = x_ext[(size_t)(m0 + tid) * KEXP + kx];
    s_w1[tid] = w1[kx * DDIM + tid];
    s_w1[tid + 256] = w1[kx * DDIM + tid + 256];
    s_b1[tid] = b1[kx * DDIM + tid];
    s_b1[tid + 256] = b1[kx * DDIM + tid + 256];

    const char* srcp[2];
    uint32_t dsto[2];
#pragma unroll
    for (int t = 0; t < 2; t++) {
        const int idx = tid + t * 256;
        const int row = idx >> 2;
        const int seg = idx & 3;
        srcp[t] = (const char*)(g_w2h + ((size_t)(kx * DDIM + n0 + row)) * DDIM) + seg * 16;
        dsto[t] = sbase + 10240 + row * 80 + seg * 16;
    }

    const int gr = tid >> 1;
    const int gh = tid & 1;
    const uint32_t ga_rel = (uint32_t)(gr * 80 + gh * 32);

    float acc[4][4][4];
#pragma unroll
    for (int i = 0; i < 4; i++)
#pragma unroll
        for (int j = 0; j < 4; j++)
#pragma unroll
            for (int q = 0; q < 4; q++) acc[i][j][q] = 0.f;

    const int arow = lane & 15, aseg = lane >> 4;
    const int brow = (lane & 7) + ((lane >> 4) & 1) * 8, bseg = (lane >> 3) & 1;
    const uint32_t offA = sbase + (wm * 64 + arow) * 80 + aseg * 16;
    const uint32_t offB = sbase + 10240 + (wn * 32 + brow) * 80 + bseg * 16;

    __syncthreads();

    auto genA = [&](int c, uint32_t so) {
        const float x = s_x[gr];
        uint32_t hv[8];
#pragma unroll
        for (int i = 0; i < 8; i++) {
            const int j = c * 32 + gh * 16 + 2 * i;
            float v0 = ftanh(fmaf(x, s_w1[j],     s_b1[j]));
            float v1 = ftanh(fmaf(x, s_w1[j + 1], s_b1[j + 1]));
            __half2 h = __floats2half2_rn(v0, v1);
            hv[i] = *reinterpret_cast<uint32_t*>(&h);
        }
        *(uint4*)(dsm + ga_rel + so)      = make_uint4(hv[0], hv[1], hv[2], hv[3]);
        *(uint4*)(dsm + ga_rel + so + 16) = make_uint4(hv[4], hv[5], hv[6], hv[7]);
    };

    genA(0, 0);
    genA(1, STAGE_BYTES);
#pragma unroll
    for (int t = 0; t < 2; t++) cpasync16(dsto[t], srcp[t]);
    CP_COMMIT();
#pragma unroll
    for (int t = 0; t < 2; t++) cpasync16(dsto[t] + STAGE_BYTES, srcp[t] + 64);
    CP_COMMIT();

    for (int c = 0; c < 16; ++c) {
        CP_WAIT1();
        __syncthreads();

        if (c + 2 < 16) {
            const uint32_t so2 = (uint32_t)((c + 2) % 3) * STAGE_BYTES;
            genA(c + 2, so2);
            const int boff = (c + 2) * 64;
#pragma unroll
            for (int t = 0; t < 2; t++)
                cpasync16(dsto[t] + so2, srcp[t] + boff);
        }
        CP_COMMIT();

        const uint32_t so = (uint32_t)(c % 3) * STAGE_BYTES;
#pragma unroll
        for (int ks = 0; ks < 2; ks++) {
            uint32_t bh[8];
            ldsm4(bh,     offB + so + ks * 32);
            ldsm4(bh + 4, offB + so + ks * 32 + 16 * 80);
#pragma unroll
            for (int mi = 0; mi < 4; mi++) {
                uint32_t ah[4];
                ldsm4(ah, offA + so + ks * 32 + mi * 16 * 80);
#pragma unroll
                for (int ni = 0; ni < 4; ni++)
                    mma16816h(acc[mi][ni], ah, bh + ni * 2);
            }
        }
    }

    const int gid = lane >> 2, qid = lane & 3;
    const float* b2k = b2 + kx * DDIM + n0 + wn * 32;
#pragma unroll
    for (int ni = 0; ni < 4; ni++) {
        const int ncol = ni * 8 + 2 * qid;
        const float bv0 = __ldg(&b2k[ncol]), bv1 = __ldg(&b2k[ncol + 1]);
#pragma unroll
        for (int mi = 0; mi < 4; mi++) {
            const int m = m0 + wm * 64 + mi * 16 + gid;
            const size_t base = (size_t)m * (KEXP * DDIM) + kx * DDIM + n0 + wn * 32 + ncol;
            __half2 v0 = __floats2half2_rn(ftanh(acc[mi][ni][0] + bv0),
                                           ftanh(acc[mi][ni][1] + bv1));
            __half2 v1 = __floats2half2_rn(ftanh(acc[mi][ni][2] + bv0),
                                           ftanh(acc[mi][ni][3] + bv1));
            *(__half2*)&g_h2[base] = v0;
            *(__half2*)&g_h2[base + (size_t)8 * (KEXP * DDIM)] = v1;
        }
    }
}

// ---------------------------------------------------------------------------
// Epilogue: fused gate logits+softmax, warp-per-expert LN, gate-weighted sum,
// theta0, x_prime.
// ---------------------------------------------------------------------------
__global__ __launch_bounds__(128) void k_epilogue(
    const float* __restrict__ ln_g, const float* __restrict__ ln_b,
    const float* __restrict__ theta0, const float* __restrict__ x_l,
    const float* __restrict__ gw2, const float* __restrict__ gb2,
    float* __restrict__ out)
{
    const int b = blockIdx.x;
    const int tid = threadIdx.x, lane = tid & 31, w = tid >> 5;
    __shared__ float s_gw2[HDIM * KEXP];
    __shared__ float s_C[HDIM];
    __shared__ float s_lg[8][16];
    __shared__ float s_g[16];
    __shared__ float s_part[4][512];
    __shared__ float s_theta[512];

#pragma unroll
    for (int i = 0; i < 8; i++)
        *(float4*)&s_gw2[(tid + i * 128) * 4] = *(const float4*)&gw2[(tid + i * 128) * 4];
    if (tid < 64)
        *(float4*)&s_C[tid * 4] = *(const float4*)&g_C[(size_t)b * HDIM + tid * 4];

    uint2 raw[4][4];
#pragma unroll
    for (int kk = 0; kk < 4; kk++) {
        const int k = w + kk * 4;
        const __half* src = g_h2 + (size_t)b * (KEXP * DDIM) + k * DDIM;
#pragma unroll
        for (int q = 0; q < 4; q++)
            raw[kk][q] = *(const uint2*)&src[q * 128 + lane * 4];
    }

    float4 lg[4], lb[4];
#pragma unroll
    for (int q = 0; q < 4; q++) {
        const int d = q * 128 + lane * 4;
        lg[q] = *(const float4*)&ln_g[d];
        lb[q] = *(const float4*)&ln_b[d];
    }
    __syncthreads();

    {
        const int k = tid & 15, jg = tid >> 4;
        float p = 0.f;
#pragma unroll
        for (int j = 0; j < 32; j++)
            p += s_C[jg * 32 + j] * s_gw2[(jg * 32 + j) * KEXP + k];
        s_lg[jg][k] = p;
    }
    __syncthreads();
    if (tid < 32) {
        const int k = lane & 15;
        float l = gb2[k];
#pragma unroll
        for (int jg = 0; jg < 8; jg++) l += s_lg[jg][k];
        float m = l;
#pragma unroll
        for (int o = 8; o > 0; o >>= 1) m = fmaxf(m, __shfl_xor_sync(0xffffffffu, m, o, 16));
        float e = expf(l - m);
        float s = e;
#pragma unroll
        for (int o = 8; o > 0; o >>= 1) s += __shfl_xor_sync(0xffffffffu, s, o, 16);
        if (lane < 16) s_g[k] = e / s;
    }

    float th[4][4];
#pragma unroll
    for (int q = 0; q < 4; q++)
#pragma unroll
        for (int j = 0; j < 4; j++) th[q][j] = 0.f;
    __syncthreads();

#pragma unroll
    for (int kk = 0; kk < 4; kk++) {
        const int k = w + kk * 4;
        float4 v[4];
        float s = 0.f, qq = 0.f;
#pragma unroll
        for (int q = 0; q < 4; q++) {
            float2 f0 = __half22float2(*reinterpret_cast<__half2*>(&raw[kk][q].x));
            float2 f1 = __half22float2(*reinterpret_cast<__half2*>(&raw[kk][q].y));
            v[q] = make_float4(f0.x, f0.y, f1.x, f1.y);
            s  += v[q].x + v[q].y + v[q].z + v[q].w;
            qq += v[q].x * v[q].x + v[q].y * v[q].y + v[q].z * v[q].z + v[q].w * v[q].w;
        }
#pragma unroll
        for (int o = 16; o > 0; o >>= 1) {
            s  += __shfl_xor_sync(0xffffffffu, s, o);
            qq += __shfl_xor_sync(0xffffffffu, qq, o);
        }
        const float mu = s * (1.f / 512.f);
        const float var = qq * (1.f / 512.f) - mu * mu;
        const float rs = rsqrtf(var + LN_EPS);
        const float gk = s_g[k];
#pragma unroll
        for (int q = 0; q < 4; q++) {
            th[q][0] += gk * ((v[q].x - mu) * rs * lg[q].x + lb[q].x);
            th[q][1] += gk * ((v[q].y - mu) * rs * lg[q].y + lb[q].y);
            th[q][2] += gk * ((v[q].z - mu) * rs * lg[q].z + lb[q].z);
            th[q][3] += gk * ((v[q].w - mu) * rs * lg[q].w + lb[q].w);
        }
    }

#pragma unroll
    for (int q = 0; q < 4; q++)
        *(float4*)&s_part[w][q * 128 + lane * 4] = make_float4(th[q][0], th[q][1], th[q][2], th[q][3]);
    __syncthreads();

    const int d0 = tid * 4;
    float4 p0 = *(float4*)&s_part[0][d0];
    float4 p1 = *(float4*)&s_part[1][d0];
    float4 p2 = *(float4*)&s_part[2][d0];
    float4 p3 = *(float4*)&s_part[3][d0];
    float4 t0 = *(const float4*)&theta0[d0];
    float4 t;
    t.x = p0.x + p1.x + p2.x + p3.x + t0.x;
    t.y = p0.y + p1.y + p2.y + p3.y + t0.y;
    t.z = p0.z + p1.z + p2.z + p3.z + t0.z;
    t.w = p0.w + p1.w + p2.w + p3.w + t0.w;
    *(float4*)&out[(size_t)BATCH * EDIM + (size_t)b * DDIM + d0] = t;
    *(float4*)&s_theta[d0] = t;
    __syncthreads();

    if (tid < EDIM) {
        float xp = 0.f;
#pragma unroll
        for (int i = 0; i < IDIM; i++)
            xp += x_l[b * IDIM + i] * s_theta[i * EDIM + tid];
        out[(size_t)b * EDIM + tid] = xp;
    }
}

// ---------------------------------------------------------------------------
extern "C" void kernel_launch(void* const* d_in, const int* in_sizes, int n_in,
                              void* d_out, int out_size)
{
    const float* h_prev = (const float*)d_in[0];
    const float* x_l    = (const float*)d_in[1];
    const float* x_ext  = (const float*)d_in[2];
    const float* w1     = (const float*)d_in[3];
    const float* b1     = (const float*)d_in[4];
    const float* w2     = (const float*)d_in[5];
    const float* b2     = (const float*)d_in[6];
    const float* gw1    = (const float*)d_in[7];
    const float* gb1    = (const float*)d_in[8];
    const float* gw2    = (const float*)d_in[9];
    const float* gb2    = (const float*)d_in[10];
    const float* ln_g   = (const float*)d_in[11];
    const float* ln_b   = (const float*)d_in[12];
    const float* theta0 = (const float*)d_in[13];
    float* out = (float*)d_out;

    cudaFuncSetAttribute(k_gemm_mma, cudaFuncAttributeMaxDynamicSharedMemorySize, GSMEM);
    cudaFuncSetAttribute(k_gate, cudaFuncAttributeMaxDynamicSharedMemorySize, GATE_SMEM);

    // Fork a side stream for the gate chain (runs concurrent with w2t + GEMM).
    cudaStream_t s1;
    cudaStreamCreateWithFlags(&s1, cudaStreamNonBlocking);
    cudaEvent_t evFork, evGate;
    cudaEventCreateWithFlags(&evFork, cudaEventDisableTiming);
    cudaEventCreateWithFlags(&evGate, cudaEventDisableTiming);

    cudaEventRecord(evFork, 0);
    cudaStreamWaitEvent(s1, evFork, 0);

    // side chain: gate inputs -> gate1 GEMM
    k_gatein<<<40, 256, 0, s1>>>(gw1, h_prev);
    k_gate<<<32, 512, GATE_SMEM, s1>>>(gb1);
    cudaEventRecord(evGate, s1);

    // main chain: w2 transpose -> main GEMM
    k_w2t<<<512, 256>>>(w2);
    k_gemm_mma<<<dim3(4, 32, KEXP), 256, GSMEM>>>(b2, x_ext, w1, b1);

    // join: epilogue needs both the GEMM and the gate chain
    cudaStreamWaitEvent(0, evGate, 0);
    k_epilogue<<<BATCH, 128>>>(ln_g, ln_b, theta0, x_l, gw2, gb2, out);

    cudaEventDestroy(evFork);
    cudaEventDestroy(evGate);
    cudaStreamDestroy(s1);
}

// round 14
// speedup vs baseline: 1.2271x; 1.1879x over previous
#include <cuda_runtime.h>
#include <cuda_bf16.h>
#include <cuda_fp16.h>
#include <math.h>
#include <stdint.h>

#define BATCH 4096
#define HDIM  256
#define KEXP  16
#define DDIM  512
#define IDIM  8
#define EDIM  64
#define LN_EPS 1e-5f

// ---------------------------------------------------------------------------
// Scratch (__device__ globals; no cudaMalloc)
// ---------------------------------------------------------------------------
__device__ __half g_w2h[(size_t)KEXP * DDIM * DDIM];   // 8MB  [k][e][d] fp16
__device__ __half g_h1h[(size_t)KEXP * BATCH * DDIM];  // 64MB [k][b][d] fp16
__device__ __half g_h2[(size_t)BATCH * KEXP * DDIM];   // 64MB [b][k][d]
__device__ __half g_gw1t[HDIM * HDIM];                 // 128KB [j][i] fp16
__device__ __half g_hph[(size_t)BATCH * HDIM];         // 2MB  h_prev fp16
__device__ float g_C[(size_t)BATCH * HDIM];            // 4MB tanh(h_prev@gw1+gb1)

// ---------------------------------------------------------------------------
// Helpers
// ---------------------------------------------------------------------------
__device__ __forceinline__ uint32_t smem_u32(const void* p) {
    uint32_t a;
    asm("{ .reg .u64 t; cvta.to.shared.u64 t, %1; cvt.u32.u64 %0, t; }"
        : "=r"(a) : "l"(p));
    return a;
}
__device__ __forceinline__ void cpasync16(uint32_t dst, const void* src) {
    asm volatile("cp.async.cg.shared.global [%0], [%1], 16;" :: "r"(dst), "l"(src));
}
#define CP_COMMIT() asm volatile("cp.async.commit_group;" ::: "memory")
#define CP_WAIT1()  asm volatile("cp.async.wait_group 1;" ::: "memory")

__device__ __forceinline__ void ldsm4(uint32_t* r, uint32_t addr) {
    asm volatile("ldmatrix.sync.aligned.m8n8.x4.shared.b16 {%0,%1,%2,%3}, [%4];"
        : "=r"(r[0]), "=r"(r[1]), "=r"(r[2]), "=r"(r[3]) : "r"(addr));
}
// fp16 x fp16 -> fp32 accum
__device__ __forceinline__ void mma16816h(float* d, const uint32_t* a,
                                          const uint32_t* b) {
    asm volatile(
        "mma.sync.aligned.m16n8k16.row.col.f32.f16.f16.f32 "
        "{%0,%1,%2,%3}, {%4,%5,%6,%7}, {%8,%9}, {%0,%1,%2,%3};"
        : "+f"(d[0]), "+f"(d[1]), "+f"(d[2]), "+f"(d[3])
        : "r"(a[0]), "r"(a[1]), "r"(a[2]), "r"(a[3]), "r"(b[0]), "r"(b[1]));
}
// fast tanh: 2 MUFU + fast div, rel err ~1e-6
__device__ __forceinline__ float ftanh(float x) {
    float ax = fabsf(x);
    float e  = __expf(-2.f * ax);
    float r  = __fdividef(1.f - e, 1.f + e);
    return copysignf(r, x);
}

// ---------------------------------------------------------------------------
// Prep kernel:
//   blocks [0,512)      : w2 transpose -> fp16 g_w2h (128d x 64e tile each)
//   blocks [512,4608)   : h1 materialize -> fp16 g_h1h
//                         (block b: all 16 experts x 512 dims for batch row b)
// ---------------------------------------------------------------------------
__global__ __launch_bounds__(256) void k_prep(
    const float* __restrict__ w2, const float* __restrict__ x_ext,
    const float* __restrict__ w1, const float* __restrict__ b1)
{
    __shared__ float s[64][129];
    const int bi = blockIdx.x;
    const int tid = threadIdx.x;

    if (bi < 512) {
        // ---- w2 transpose -> fp16 ----
        const int k = bi >> 5;
        const int t = bi & 31;
        const int e0 = (t & 7) * 64;
        const int dblk = (t >> 3) * 128;

        for (int i = tid; i < 128 * 64; i += 256) {
            int dl = i >> 6, el = i & 63;
            s[el][dl] = w2[((size_t)k * DDIM + dblk + dl) * DDIM + e0 + el];
        }
        __syncthreads();

        const int el = tid >> 2, cp = tid & 3;
        uint32_t hv[16];
#pragma unroll
        for (int jj = 0; jj < 16; jj++) {
            __half a = __float2half_rn(s[el][cp * 32 + 2 * jj]);
            __half b = __float2half_rn(s[el][cp * 32 + 2 * jj + 1]);
            hv[jj] = ((uint32_t)__half_as_ushort(b) << 16) | __half_as_ushort(a);
        }
        const size_t base = ((size_t)k * DDIM + e0 + el) * DDIM + dblk + cp * 32;
        uint4* dh = (uint4*)&g_w2h[base];
        dh[0] = make_uint4(hv[0], hv[1], hv[2], hv[3]);
        dh[1] = make_uint4(hv[4], hv[5], hv[6], hv[7]);
        dh[2] = make_uint4(hv[8], hv[9], hv[10], hv[11]);
        dh[3] = make_uint4(hv[12], hv[13], hv[14], hv[15]);
    } else {
        // ---- h1 materialize: b = bi-512, 16 experts x 512 dims ----
        const int b = bi - 512;
        float* xs = (float*)s;
        if (tid < KEXP) xs[tid] = x_ext[b * KEXP + tid];
        __syncthreads();
#pragma unroll
        for (int i = 0; i < 8; i++) {
            const int j = tid + i * 256;       // 0..2047 quads
            const int k = j >> 7;
            const int d0 = (j & 127) * 4;
            const float x = xs[k];
            float4 w  = *(const float4*)&w1[k * DDIM + d0];
            float4 bb = *(const float4*)&b1[k * DDIM + d0];
            float v0 = ftanh(fmaf(x, w.x, bb.x));
            float v1 = ftanh(fmaf(x, w.y, bb.y));
            float v2 = ftanh(fmaf(x, w.z, bb.z));
            float v3 = ftanh(fmaf(x, w.w, bb.w));
            __half2 h0 = __floats2half2_rn(v0, v1);
            __half2 h1v = __floats2half2_rn(v2, v3);
            uint2 o = make_uint2(*reinterpret_cast<uint32_t*>(&h0),
                                 *reinterpret_cast<uint32_t*>(&h1v));
            *(uint2*)&g_h1h[((size_t)k * BATCH + b) * DDIM + d0] = o;
        }
    }
}

// ---------------------------------------------------------------------------
// Gate inputs: blocks [0,8) gw1 transpose -> fp16; blocks [8,40) h_prev -> fp16
// ---------------------------------------------------------------------------
__global__ __launch_bounds__(256) void k_gatein(
    const float* __restrict__ gw1, const float* __restrict__ h_prev)
{
    __shared__ float s[64][129];
    const int bi = blockIdx.x;
    const int tid = threadIdx.x;

    if (bi < 8) {
        const int j0 = (bi & 3) * 64;
        const int i0 = (bi >> 2) * 128;

        for (int i = tid; i < 128 * 64; i += 256) {
            int il = i >> 6, jl = i & 63;
            s[jl][il] = gw1[(size_t)(i0 + il) * HDIM + j0 + jl];
        }
        __syncthreads();

        const int jl = tid >> 2, cp = tid & 3;
        uint32_t hv[16];
#pragma unroll
        for (int jj = 0; jj < 16; jj++) {
            __half a = __float2half_rn(s[jl][cp * 32 + 2 * jj]);
            __half b = __float2half_rn(s[jl][cp * 32 + 2 * jj + 1]);
            hv[jj] = ((uint32_t)__half_as_ushort(b) << 16) | __half_as_ushort(a);
        }
        const size_t base = (size_t)(j0 + jl) * HDIM + i0 + cp * 32;
        uint4* dh = (uint4*)&g_gw1t[base];
        dh[0] = make_uint4(hv[0], hv[1], hv[2], hv[3]);
        dh[1] = make_uint4(hv[4], hv[5], hv[6], hv[7]);
        dh[2] = make_uint4(hv[8], hv[9], hv[10], hv[11]);
        dh[3] = make_uint4(hv[12], hv[13], hv[14], hv[15]);
    } else {
        const int t = bi - 8;              // 0..31
        const size_t base = (size_t)t * 32768;
#pragma unroll 4
        for (int i = tid; i < 8192; i += 256) {
            float4 v = *(const float4*)&h_prev[base + i * 4];
            __half2 h0 = __floats2half2_rn(v.x, v.y);
            __half2 h1 = __floats2half2_rn(v.z, v.w);
            uint2 o = make_uint2(*reinterpret_cast<uint32_t*>(&h0),
                                 *reinterpret_cast<uint32_t*>(&h1));
            *(uint2*)&g_hph[base + i * 4] = o;
        }
    }
}

// ---------------------------------------------------------------------------
// gate1 HMMA GEMM: g_C = tanh(h_prev @ gw1 + gb1).  M=4096, N=256, K=256.
// ---------------------------------------------------------------------------
#define GSTAGE 30720
#define GATE_SMEM (3 * GSTAGE)

__global__ __launch_bounds__(512, 1) void k_gate(const float* __restrict__ gb1)
{
    extern __shared__ char dsm[];
    const int m0 = blockIdx.x * 128;
    const int tid = threadIdx.x, lane = tid & 31, wid = tid >> 5;
    const int wm = wid >> 3, wn = wid & 7;
    const uint32_t sbase = smem_u32(dsm);

    const char* srcp[3];
    uint32_t dsto[3];
#pragma unroll
    for (int t = 0; t < 3; t++) {
        const int idx = tid + t * 512;
        if (idx < 512) {
            const int row = idx >> 2, seg = idx & 3;
            srcp[t] = (const char*)(g_hph + (size_t)(m0 + row) * HDIM) + seg * 16;
            dsto[t] = sbase + row * 80 + seg * 16;
        } else {
            const int j = idx - 512;
            const int row = j >> 2, seg = j & 3;
            srcp[t] = (const char*)(g_gw1t + (size_t)row * HDIM) + seg * 16;
            dsto[t] = sbase + 10240 + row * 80 + seg * 16;
        }
    }

    float acc[4][4][4];
#pragma unroll
    for (int i = 0; i < 4; i++)
#pragma unroll
        for (int j = 0; j < 4; j++)
#pragma unroll
            for (int q = 0; q < 4; q++) acc[i][j][q] = 0.f;

    const int arow = lane & 15, aseg = lane >> 4;
    const int brow = (lane & 7) + ((lane >> 4) & 1) * 8, bseg = (lane >> 3) & 1;
    const uint32_t offA = sbase + (wm * 64 + arow) * 80 + aseg * 16;
    const uint32_t offB = sbase + 10240 + (wn * 32 + brow) * 80 + bseg * 16;

#pragma unroll
    for (int t = 0; t < 3; t++) cpasync16(dsto[t], srcp[t]);
    CP_COMMIT();
#pragma unroll
    for (int t = 0; t < 3; t++) cpasync16(dsto[t] + GSTAGE, srcp[t] + 64);
    CP_COMMIT();

    for (int c = 0; c < 8; ++c) {
        CP_WAIT1();
        __syncthreads();

        if (c + 2 < 8) {
            const uint32_t so2 = (uint32_t)((c + 2) % 3) * GSTAGE;
            const int boff = (c + 2) * 64;
#pragma unroll
            for (int t = 0; t < 3; t++)
                cpasync16(dsto[t] + so2, srcp[t] + boff);
        }
        CP_COMMIT();

        const uint32_t so = (uint32_t)(c % 3) * GSTAGE;
#pragma unroll
        for (int ks = 0; ks < 2; ks++) {
            uint32_t bh[8];
            ldsm4(bh,     offB + so + ks * 32);
            ldsm4(bh + 4, offB + so + ks * 32 + 16 * 80);
#pragma unroll
            for (int mi = 0; mi < 4; mi++) {
                uint32_t ah[4];
                ldsm4(ah, offA + so + ks * 32 + mi * 16 * 80);
#pragma unroll
                for (int ni = 0; ni < 4; ni++)
                    mma16816h(acc[mi][ni], ah, bh + ni * 2);
            }
        }
    }

    const int gid = lane >> 2, qid = lane & 3;
    const float* gbk = gb1 + wn * 32;
#pragma unroll
    for (int ni = 0; ni < 4; ni++) {
        const int ncol = ni * 8 + 2 * qid;
        const float bv0 = __ldg(&gbk[ncol]), bv1 = __ldg(&gbk[ncol + 1]);
#pragma unroll
        for (int mi = 0; mi < 4; mi++) {
            const int m = m0 + wm * 64 + mi * 16 + gid;
            float* dst = &g_C[(size_t)m * HDIM + wn * 32 + ncol];
            *(float2*)dst = make_float2(ftanh(acc[mi][ni][0] + bv0),
                                        ftanh(acc[mi][ni][1] + bv1));
            *(float2*)(dst + 8 * HDIM) = make_float2(ftanh(acc[mi][ni][2] + bv0),
                                                     ftanh(acc[mi][ni][3] + bv1));
        }
    }
}

// ---------------------------------------------------------------------------
// Main GEMM: PURE pipeline — cp.async A (g_h1h) + B (g_w2h), ldsm, HMMA.
// 128x128 tile, 256 threads (8 warps, warp tile 64x32), k-chunk 32,
// 3-stage ring, 2 CTAs/SM. Stage (20480B): A[128][80] @0, B[128][80] @10240.
// ---------------------------------------------------------------------------
#define STAGE_BYTES 20480
#define GSMEM (3 * STAGE_BYTES)   // 61440

__global__ __launch_bounds__(256, 2) void k_gemm_mma(const float* __restrict__ b2)
{
    extern __shared__ char dsm[];
    const int n0 = blockIdx.x * 128;
    const int m0 = blockIdx.y * 128;
    const int kx = blockIdx.z;
    const int tid = threadIdx.x, lane = tid & 31, wid = tid >> 5;
    const int wm = wid >> 2, wn = wid & 3;
    const uint32_t sbase = smem_u32(dsm);

    // cp.async slots: A 512 segs + B 512 segs per stage, 4 per thread
    const char* srcp[4];
    uint32_t dsto[4];
#pragma unroll
    for (int t = 0; t < 4; t++) {
        const int idx = tid + t * 256;
        if (idx < 512) {
            const int row = idx >> 2, seg = idx & 3;
            srcp[t] = (const char*)(g_h1h + ((size_t)kx * BATCH + m0 + row) * DDIM) + seg * 16;
            dsto[t] = sbase + row * 80 + seg * 16;
        } else {
            const int j = idx - 512;
            const int row = j >> 2, seg = j & 3;
            srcp[t] = (const char*)(g_w2h + ((size_t)(kx * DDIM + n0 + row)) * DDIM) + seg * 16;
            dsto[t] = sbase + 10240 + row * 80 + seg * 16;
        }
    }

    float acc[4][4][4];
#pragma unroll
    for (int i = 0; i < 4; i++)
#pragma unroll
        for (int j = 0; j < 4; j++)
#pragma unroll
            for (int q = 0; q < 4; q++) acc[i][j][q] = 0.f;

    const int arow = lane & 15, aseg = lane >> 4;
    const int brow = (lane & 7) + ((lane >> 4) & 1) * 8, bseg = (lane >> 3) & 1;
    const uint32_t offA = sbase + (wm * 64 + arow) * 80 + aseg * 16;
    const uint32_t offB = sbase + 10240 + (wn * 32 + brow) * 80 + bseg * 16;

    // prologue: chunks 0,1 (chunk c -> +c*64B in src rows)
#pragma unroll
    for (int t = 0; t < 4; t++) cpasync16(dsto[t], srcp[t]);
    CP_COMMIT();
#pragma unroll
    for (int t = 0; t < 4; t++) cpasync16(dsto[t] + STAGE_BYTES, srcp[t] + 64);
    CP_COMMIT();

    for (int c = 0; c < 16; ++c) {
        CP_WAIT1();            // chunk c landed
        __syncthreads();       // stage (c+2)%3 free (prev MMA done everywhere)

        if (c + 2 < 16) {
            const uint32_t so2 = (uint32_t)((c + 2) % 3) * STAGE_BYTES;
            const int boff = (c + 2) * 64;
#pragma unroll
            for (int t = 0; t < 4; t++)
                cpasync16(dsto[t] + so2, srcp[t] + boff);
        }
        CP_COMMIT();

        const uint32_t so = (uint32_t)(c % 3) * STAGE_BYTES;
#pragma unroll
        for (int ks = 0; ks < 2; ks++) {
            uint32_t bh[8];
            ldsm4(bh,     offB + so + ks * 32);
            ldsm4(bh + 4, offB + so + ks * 32 + 16 * 80);
#pragma unroll
            for (int mi = 0; mi < 4; mi++) {
                uint32_t ah[4];
                ldsm4(ah, offA + so + ks * 32 + mi * 16 * 80);
#pragma unroll
                for (int ni = 0; ni < 4; ni++)
                    mma16816h(acc[mi][ni], ah, bh + ni * 2);
            }
        }
    }

    // epilogue: + b2, tanh, store fp16 to g_h2[b][k][d]
    const int gid = lane >> 2, qid = lane & 3;
    const float* b2k = b2 + kx * DDIM + n0 + wn * 32;
#pragma unroll
    for (int ni = 0; ni < 4; ni++) {
        const int ncol = ni * 8 + 2 * qid;
        const float bv0 = __ldg(&b2k[ncol]), bv1 = __ldg(&b2k[ncol + 1]);
#pragma unroll
        for (int mi = 0; mi < 4; mi++) {
            const int m = m0 + wm * 64 + mi * 16 + gid;
            const size_t base = (size_t)m * (KEXP * DDIM) + kx * DDIM + n0 + wn * 32 + ncol;
            __half2 v0 = __floats2half2_rn(ftanh(acc[mi][ni][0] + bv0),
                                           ftanh(acc[mi][ni][1] + bv1));
            __half2 v1 = __floats2half2_rn(ftanh(acc[mi][ni][2] + bv0),
                                           ftanh(acc[mi][ni][3] + bv1));
            *(__half2*)&g_h2[base] = v0;
            *(__half2*)&g_h2[base + (size_t)8 * (KEXP * DDIM)] = v1;
        }
    }
}

// ---------------------------------------------------------------------------
// Epilogue: fused gate logits+softmax, warp-per-expert LN, gate-weighted sum,
// theta0, x_prime.
// ---------------------------------------------------------------------------
__global__ __launch_bounds__(128) void k_epilogue(
    const float* __restrict__ ln_g, const float* __restrict__ ln_b,
    const float* __restrict__ theta0, const float* __restrict__ x_l,
    const float* __restrict__ gw2, const float* __restrict__ gb2,
    float* __restrict__ out)
{
    const int b = blockIdx.x;
    const int tid = threadIdx.x, lane = tid & 31, w = tid >> 5;
    __shared__ float s_gw2[HDIM * KEXP];
    __shared__ float s_C[HDIM];
    __shared__ float s_lg[8][16];
    __shared__ float s_g[16];
    __shared__ float s_part[4][512];
    __shared__ float s_theta[512];

#pragma unroll
    for (int i = 0; i < 8; i++)
        *(float4*)&s_gw2[(tid + i * 128) * 4] = *(const float4*)&gw2[(tid + i * 128) * 4];
    if (tid < 64)
        *(float4*)&s_C[tid * 4] = *(const float4*)&g_C[(size_t)b * HDIM + tid * 4];

    uint2 raw[4][4];
#pragma unroll
    for (int kk = 0; kk < 4; kk++) {
        const int k = w + kk * 4;
        const __half* src = g_h2 + (size_t)b * (KEXP * DDIM) + k * DDIM;
#pragma unroll
        for (int q = 0; q < 4; q++)
            raw[kk][q] = *(const uint2*)&src[q * 128 + lane * 4];
    }

    float4 lg[4], lb[4];
#pragma unroll
    for (int q = 0; q < 4; q++) {
        const int d = q * 128 + lane * 4;
        lg[q] = *(const float4*)&ln_g[d];
        lb[q] = *(const float4*)&ln_b[d];
    }
    __syncthreads();

    {
        const int k = tid & 15, jg = tid >> 4;
        float p = 0.f;
#pragma unroll
        for (int j = 0; j < 32; j++)
            p += s_C[jg * 32 + j] * s_gw2[(jg * 32 + j) * KEXP + k];
        s_lg[jg][k] = p;
    }
    __syncthreads();
    if (tid < 32) {
        const int k = lane & 15;
        float l = gb2[k];
#pragma unroll
        for (int jg = 0; jg < 8; jg++) l += s_lg[jg][k];
        float m = l;
#pragma unroll
        for (int o = 8; o > 0; o >>= 1) m = fmaxf(m, __shfl_xor_sync(0xffffffffu, m, o, 16));
        float e = expf(l - m);
        float s = e;
#pragma unroll
        for (int o = 8; o > 0; o >>= 1) s += __shfl_xor_sync(0xffffffffu, s, o, 16);
        if (lane < 16) s_g[k] = e / s;
    }

    float th[4][4];
#pragma unroll
    for (int q = 0; q < 4; q++)
#pragma unroll
        for (int j = 0; j < 4; j++) th[q][j] = 0.f;
    __syncthreads();

#pragma unroll
    for (int kk = 0; kk < 4; kk++) {
        const int k = w + kk * 4;
        float4 v[4];
        float s = 0.f, qq = 0.f;
#pragma unroll
        for (int q = 0; q < 4; q++) {
            float2 f0 = __half22float2(*reinterpret_cast<__half2*>(&raw[kk][q].x));
            float2 f1 = __half22float2(*reinterpret_cast<__half2*>(&raw[kk][q].y));
            v[q] = make_float4(f0.x, f0.y, f1.x, f1.y);
            s  += v[q].x + v[q].y + v[q].z + v[q].w;
            qq += v[q].x * v[q].x + v[q].y * v[q].y + v[q].z * v[q].z + v[q].w * v[q].w;
        }
#pragma unroll
        for (int o = 16; o > 0; o >>= 1) {
            s  += __shfl_xor_sync(0xffffffffu, s, o);
            qq += __shfl_xor_sync(0xffffffffu, qq, o);
        }
        const float mu = s * (1.f / 512.f);
        const float var = qq * (1.f / 512.f) - mu * mu;
        const float rs = rsqrtf(var + LN_EPS);
        const float gk = s_g[k];
#pragma unroll
        for (int q = 0; q < 4; q++) {
            th[q][0] += gk * ((v[q].x - mu) * rs * lg[q].x + lb[q].x);
            th[q][1] += gk * ((v[q].y - mu) * rs * lg[q].y + lb[q].y);
            th[q][2] += gk * ((v[q].z - mu) * rs * lg[q].z + lb[q].z);
            th[q][3] += gk * ((v[q].w - mu) * rs * lg[q].w + lb[q].w);
        }
    }

#pragma unroll
    for (int q = 0; q < 4; q++)
        *(float4*)&s_part[w][q * 128 + lane * 4] = make_float4(th[q][0], th[q][1], th[q][2], th[q][3]);
    __syncthreads();

    const int d0 = tid * 4;
    float4 p0 = *(float4*)&s_part[0][d0];
    float4 p1 = *(float4*)&s_part[1][d0];
    float4 p2 = *(float4*)&s_part[2][d0];
    float4 p3 = *(float4*)&s_part[3][d0];
    float4 t0 = *(const float4*)&theta0[d0];
    float4 t;
    t.x = p0.x + p1.x + p2.x + p3.x + t0.x;
    t.y = p0.y + p1.y + p2.y + p3.y + t0.y;
    t.z = p0.z + p1.z + p2.z + p3.z + t0.z;
    t.w = p0.w + p1.w + p2.w + p3.w + t0.w;
    *(float4*)&out[(size_t)BATCH * EDIM + (size_t)b * DDIM + d0] = t;
    *(float4*)&s_theta[d0] = t;
    __syncthreads();

    if (tid < EDIM) {
        float xp = 0.f;
#pragma unroll
        for (int i = 0; i < IDIM; i++)
            xp += x_l[b * IDIM + i] * s_theta[i * EDIM + tid];
        out[(size_t)b * EDIM + tid] = xp;
    }
}

// ---------------------------------------------------------------------------
extern "C" void kernel_launch(void* const* d_in, const int* in_sizes, int n_in,
                              void* d_out, int out_size)
{
    const float* h_prev = (const float*)d_in[0];
    const float* x_l    = (const float*)d_in[1];
    const float* x_ext  = (const float*)d_in[2];
    const float* w1     = (const float*)d_in[3];
    const float* b1     = (const float*)d_in[4];
    const float* w2     = (const float*)d_in[5];
    const float* b2     = (const float*)d_in[6];
    const float* gw1    = (const float*)d_in[7];
    const float* gb1    = (const float*)d_in[8];
    const float* gw2    = (const float*)d_in[9];
    const float* gb2    = (const float*)d_in[10];
    const float* ln_g   = (const float*)d_in[11];
    const float* ln_b   = (const float*)d_in[12];
    const float* theta0 = (const float*)d_in[13];
    float* out = (float*)d_out;

    cudaFuncSetAttribute(k_gemm_mma, cudaFuncAttributeMaxDynamicSharedMemorySize, GSMEM);
    cudaFuncSetAttribute(k_gate, cudaFuncAttributeMaxDynamicSharedMemorySize, GATE_SMEM);

    // Fork a side stream for the gate chain (runs concurrent with prep + GEMM).
    cudaStream_t s1;
    cudaStreamCreateWithFlags(&s1, cudaStreamNonBlocking);
    cudaEvent_t evFork, evGate;
    cudaEventCreateWithFlags(&evFork, cudaEventDisableTiming);
    cudaEventCreateWithFlags(&evGate, cudaEventDisableTiming);

    cudaEventRecord(evFork, 0);
    cudaStreamWaitEvent(s1, evFork, 0);

    // side chain: gate inputs -> gate1 GEMM
    k_gatein<<<40, 256, 0, s1>>>(gw1, h_prev);
    k_gate<<<32, 512, GATE_SMEM, s1>>>(gb1);
    cudaEventRecord(evGate, s1);

    // main chain: w2 transpose + h1 materialize -> pure GEMM
    k_prep<<<512 + BATCH, 256>>>(w2, x_ext, w1, b1);
    k_gemm_mma<<<dim3(4, 32, KEXP), 256, GSMEM>>>(b2);

    // join: epilogue needs both the GEMM and the gate chain
    cudaStreamWaitEvent(0, evGate, 0);
    k_epilogue<<<BATCH, 128>>>(ln_g, ln_b, theta0, x_l, gw2, gb2, out);

    cudaEventDestroy(evFork);
    cudaEventDestroy(evGate);
    cudaStreamDestroy(s1);
}